// round 2
// baseline (speedup 1.0000x reference)
#include <cuda_runtime.h>
#include <cuda_bf16.h>
#include <cstdint>

#define N_USERS 100000
#define N_ITEMS 50000
#define N_NODES 150000
#define D 64
#define DV 16              // D / 4 float4s per node row
#define NNZ 4800000

// Scratch: double buffer for hop embeddings (38.4 MB each). Device globals
// are the sanctioned no-alloc scratch mechanism.
__device__ float4 g_bufA[N_NODES * DV];
__device__ float4 g_bufB[N_NODES * DV];

// ---------------------------------------------------------------------------
// ego = concat(user_embed, item_embed), vectorized float4
// ---------------------------------------------------------------------------
__global__ void __launch_bounds__(256) concat_kernel(
    const float4* __restrict__ u, const float4* __restrict__ it,
    float4* __restrict__ ego)
{
    int i = blockIdx.x * blockDim.x + threadIdx.x;
    const int total = N_NODES * DV;
    const int nu = N_USERS * DV;
    if (i < total) {
        ego[i] = (i < nu) ? u[i] : it[i - nu];
    }
}

// ---------------------------------------------------------------------------
// Y[row] += vals * X[col]  (atomic scatter SpMM)
// 16 threads per edge, each thread owns one float4 of the 64-wide row.
// red.global.add.v4.f32 = one atomic instruction per 16B (sm_90+).
// ---------------------------------------------------------------------------
__global__ void __launch_bounds__(256) spmm_atomic_kernel(
    const int* __restrict__ row, const int* __restrict__ col,
    const float* __restrict__ vals,
    const float4* __restrict__ x, float4* __restrict__ y)
{
    long long gtid = (long long)blockIdx.x * blockDim.x + threadIdx.x;
    int edge = (int)(gtid >> 4);
    int lane = (int)(gtid & 15);
    if (edge >= NNZ) return;

    int   r = __ldg(row + edge);
    int   c = __ldg(col + edge);
    float v = __ldg(vals + edge);

    float4 xv = __ldg(x + c * DV + lane);
    float4 o;
    o.x = xv.x * v; o.y = xv.y * v; o.z = xv.z * v; o.w = xv.w * v;

    float4* dst = y + r * DV + lane;
    asm volatile("red.global.add.v4.f32 [%0], {%1, %2, %3, %4};"
                 :: "l"(dst), "f"(o.x), "f"(o.y), "f"(o.z), "f"(o.w)
                 : "memory");
}

// ---------------------------------------------------------------------------
// Accumulate hop output into d_out.
//   out_all  (d_out first half):  = y/3 on first hop, += y/3 after
//   out_layer (d_out second half): = y on hop 0 only
// ---------------------------------------------------------------------------
__global__ void __launch_bounds__(256) post_kernel(
    const float4* __restrict__ y, float4* __restrict__ out_all,
    float4* __restrict__ out_layer, int first)
{
    int i = blockIdx.x * blockDim.x + threadIdx.x;
    const int total = N_NODES * DV;
    if (i >= total) return;

    float4 v = y[i];
    const float s = 1.0f / 3.0f;
    float4 a;
    a.x = v.x * s; a.y = v.y * s; a.z = v.z * s; a.w = v.w * s;

    if (first) {
        out_all[i] = a;
        out_layer[i] = v;
    } else {
        float4 cur = out_all[i];
        cur.x += a.x; cur.y += a.y; cur.z += a.z; cur.w += a.w;
        out_all[i] = cur;
    }
}

// ---------------------------------------------------------------------------
// Host orchestration (graph-capturable: kernels + memset only)
// ---------------------------------------------------------------------------
extern "C" void kernel_launch(void* const* d_in, const int* in_sizes, int n_in,
                              void* d_out, int out_size)
{
    const float4* user_e = (const float4*)d_in[0];
    const float4* item_e = (const float4*)d_in[1];
    const int*    row    = (const int*)d_in[2];
    const int*    col    = (const int*)d_in[3];
    const float*  vals   = (const float*)d_in[4];

    float4* out_all   = (float4*)d_out;                    // [N_NODES, 64] / 4
    float4* out_layer = out_all + N_NODES * DV;            // [N_NODES, 64] / 4

    float4 *bufA, *bufB;
    cudaGetSymbolAddress((void**)&bufA, g_bufA);
    cudaGetSymbolAddress((void**)&bufB, g_bufB);

    const int nodeV = N_NODES * DV;                        // 2.4M float4s
    const int nodeBlocks = (nodeV + 255) / 256;
    const long long spmmThreads = (long long)NNZ * 16;
    const int spmmBlocks = (int)((spmmThreads + 255) / 256);
    const size_t bufBytes = (size_t)nodeV * sizeof(float4);

    // ego -> bufA
    concat_kernel<<<nodeBlocks, 256>>>(user_e, item_e, bufA);

    // hop 1: bufA -> bufB
    cudaMemsetAsync(bufB, 0, bufBytes);
    spmm_atomic_kernel<<<spmmBlocks, 256>>>(row, col, vals, bufA, bufB);
    post_kernel<<<nodeBlocks, 256>>>(bufB, out_all, out_layer, 1);

    // hop 2: bufB -> bufA
    cudaMemsetAsync(bufA, 0, bufBytes);
    spmm_atomic_kernel<<<spmmBlocks, 256>>>(row, col, vals, bufB, bufA);
    post_kernel<<<nodeBlocks, 256>>>(bufA, out_all, out_layer, 0);

    // hop 3: bufA -> bufB
    cudaMemsetAsync(bufB, 0, bufBytes);
    spmm_atomic_kernel<<<spmmBlocks, 256>>>(row, col, vals, bufA, bufB);
    post_kernel<<<nodeBlocks, 256>>>(bufB, out_all, out_layer, 0);
}

// round 4
// speedup vs baseline: 2.1806x; 2.1806x over previous
#include <cuda_runtime.h>
#include <cuda_bf16.h>
#include <cstdint>

#define N_USERS 100000
#define N_ITEMS 50000
#define N_NODES 150000
#define D 64
#define DF2 32             // D/2 float2s per node row
#define NNZ 4800000
#define SCAN_BLK 1024
#define NBLK ((N_NODES + SCAN_BLK - 1) / SCAN_BLK)   // 147

// ---------------- device-global scratch (no allocations allowed) -----------
__device__ float2 g_bufA[N_NODES * DF2];   // 38.4 MB
__device__ float2 g_bufB[N_NODES * DF2];   // 38.4 MB
__device__ int2   g_colv[NNZ];             // 38.4 MB: {col, val-bits} per edge, CSR order
__device__ int    g_cnt[N_NODES];
__device__ int    g_rowptr[N_NODES + 1];
__device__ int    g_wp[N_NODES];
__device__ int    g_bsum[NBLK];

// ---------------------------------------------------------------------------
// CSR build: histogram -> 2-level exclusive scan -> scatter permute
// ---------------------------------------------------------------------------
__global__ void __launch_bounds__(256) hist_kernel(const int* __restrict__ row)
{
    int e = blockIdx.x * blockDim.x + threadIdx.x;
    if (e < NNZ) atomicAdd(&g_cnt[row[e]], 1);
}

__global__ void __launch_bounds__(SCAN_BLK) scan1_kernel()
{
    __shared__ int s[SCAN_BLK];
    int gid = blockIdx.x * SCAN_BLK + threadIdx.x;
    int c = (gid < N_NODES) ? g_cnt[gid] : 0;
    s[threadIdx.x] = c;
    __syncthreads();
    #pragma unroll
    for (int off = 1; off < SCAN_BLK; off <<= 1) {
        int t = (threadIdx.x >= off) ? s[threadIdx.x - off] : 0;
        __syncthreads();
        s[threadIdx.x] += t;
        __syncthreads();
    }
    if (gid < N_NODES) g_rowptr[gid] = s[threadIdx.x] - c;   // exclusive within block
    if (threadIdx.x == SCAN_BLK - 1) g_bsum[blockIdx.x] = s[SCAN_BLK - 1];
}

__global__ void __launch_bounds__(256) scan2_kernel()
{
    __shared__ int s[256];
    int c = (threadIdx.x < NBLK) ? g_bsum[threadIdx.x] : 0;
    s[threadIdx.x] = c;
    __syncthreads();
    #pragma unroll
    for (int off = 1; off < 256; off <<= 1) {
        int t = (threadIdx.x >= off) ? s[threadIdx.x - off] : 0;
        __syncthreads();
        s[threadIdx.x] += t;
        __syncthreads();
    }
    if (threadIdx.x < NBLK) g_bsum[threadIdx.x] = s[threadIdx.x] - c; // exclusive
}

__global__ void __launch_bounds__(256) scan3_kernel()
{
    int i = blockIdx.x * blockDim.x + threadIdx.x;
    if (i < N_NODES) {
        int v = g_rowptr[i] + g_bsum[i >> 10];
        g_rowptr[i] = v;
        g_wp[i] = v;
    }
    if (i == 0) g_rowptr[N_NODES] = NNZ;
}

__global__ void __launch_bounds__(256) scatter_kernel(
    const int* __restrict__ row, const int* __restrict__ col,
    const float* __restrict__ vals)
{
    int e = blockIdx.x * blockDim.x + threadIdx.x;
    if (e >= NNZ) return;
    int r = row[e];
    int pos = atomicAdd(&g_wp[r], 1);
    g_colv[pos] = make_int2(col[e], __float_as_int(vals[e]));
}

// ---------------------------------------------------------------------------
// Gather SpMM hop: one warp per output node, each lane owns one float2.
// MODE 1: x = concat(u,it) virtual; writes y, out_all = y/3, out_layer = y
// MODE 2: reads x buffer;           writes y, out_all += y/3
// MODE 3: reads x buffer;           out_all += y/3 (no y write)
// ---------------------------------------------------------------------------
template<int MODE>
__global__ void __launch_bounds__(256) hop_kernel(
    const float2* __restrict__ x,
    const float2* __restrict__ u, const float2* __restrict__ it,
    float2* __restrict__ y,
    float2* __restrict__ out_all, float2* __restrict__ out_layer)
{
    int warp = (blockIdx.x * blockDim.x + threadIdx.x) >> 5;
    int lane = threadIdx.x & 31;
    if (warp >= N_NODES) return;

    int beg = g_rowptr[warp];
    int end = g_rowptr[warp + 1];

    float ax = 0.0f, ay = 0.0f;
    #pragma unroll 4
    for (int e = beg; e < end; e++) {
        int2 cv = __ldg(&g_colv[e]);               // warp-uniform broadcast
        float v = __int_as_float(cv.y);
        const float2* src;
        if (MODE == 1) {
            src = (cv.x < N_USERS)
                ? (u  + (size_t)cv.x * DF2)
                : (it + (size_t)(cv.x - N_USERS) * DF2);
        } else {
            src = x + (size_t)cv.x * DF2;
        }
        float2 xv = __ldg(src + lane);             // 256B coalesced per warp
        ax = fmaf(v, xv.x, ax);
        ay = fmaf(v, xv.y, ay);
    }

    size_t o = (size_t)warp * DF2 + lane;
    const float s = 1.0f / 3.0f;
    if (MODE == 1) {
        y[o]         = make_float2(ax, ay);
        out_all[o]   = make_float2(ax * s, ay * s);
        out_layer[o] = make_float2(ax, ay);
    } else if (MODE == 2) {
        y[o] = make_float2(ax, ay);
        float2 cu = out_all[o];
        out_all[o] = make_float2(cu.x + ax * s, cu.y + ay * s);
    } else {
        float2 cu = out_all[o];
        out_all[o] = make_float2(cu.x + ax * s, cu.y + ay * s);
    }
}

// ---------------------------------------------------------------------------
extern "C" void kernel_launch(void* const* d_in, const int* in_sizes, int n_in,
                              void* d_out, int out_size)
{
    const float2* user_e = (const float2*)d_in[0];
    const float2* item_e = (const float2*)d_in[1];
    const int*    row    = (const int*)d_in[2];
    const int*    col    = (const int*)d_in[3];
    const float*  vals   = (const float*)d_in[4];

    float2* out_all   = (float2*)d_out;
    float2* out_layer = out_all + (size_t)N_NODES * DF2;

    void* cntAddr;
    cudaGetSymbolAddress(&cntAddr, g_cnt);
    float2 *bufA, *bufB;
    cudaGetSymbolAddress((void**)&bufA, g_bufA);
    cudaGetSymbolAddress((void**)&bufB, g_bufB);

    const int edgeBlocks = (NNZ + 255) / 256;              // 18750
    const int nodeBlocks = (N_NODES + 255) / 256;          // 586
    const int hopBlocks  = (N_NODES * 32 + 255) / 256;     // 18750

    // ---- CSR build ----
    cudaMemsetAsync(cntAddr, 0, N_NODES * sizeof(int));
    hist_kernel<<<edgeBlocks, 256>>>(row);
    scan1_kernel<<<NBLK, SCAN_BLK>>>();
    scan2_kernel<<<1, 256>>>();
    scan3_kernel<<<nodeBlocks, 256>>>();
    scatter_kernel<<<edgeBlocks, 256>>>(row, col, vals);

    // ---- 3 hops, fused epilogues, no atomics, no memsets ----
    hop_kernel<1><<<hopBlocks, 256>>>(nullptr, user_e, item_e, bufA,
                                      out_all, out_layer);
    hop_kernel<2><<<hopBlocks, 256>>>(bufA, nullptr, nullptr, bufB,
                                      out_all, out_layer);
    hop_kernel<3><<<hopBlocks, 256>>>(bufB, nullptr, nullptr, nullptr,
                                      out_all, out_layer);
}

// round 6
// speedup vs baseline: 2.2499x; 1.0318x over previous
#include <cuda_runtime.h>
#include <cuda_fp16.h>
#include <cstdint>

#define N_USERS 100000
#define N_ITEMS 50000
#define N_NODES 150000
#define D 64
#define DH2 32             // D/2 half2 per node row (128B)
#define DF2 32             // D/2 float2 per node row (256B)
#define NNZ 4800000
#define SCAN_BLK 1024
#define NBLK ((N_NODES + SCAN_BLK - 1) / SCAN_BLK)   // 147

// ---------------- device-global scratch (no allocations allowed) -----------
__device__ __half2 g_egoH[N_NODES * DH2];  // 19.2 MB fp16 ego
__device__ __half2 g_bufA[N_NODES * DH2];  // 19.2 MB hop-1 out (fp16)
__device__ __half2 g_bufB[N_NODES * DH2];  // 19.2 MB hop-2 out (fp16)
__device__ int2    g_colv[NNZ];            // 38.4 MB {col, val-bits}, CSR order
__device__ int     g_cnt[N_NODES];
__device__ int     g_rowptr[N_NODES + 1];
__device__ int     g_wp[N_NODES];
__device__ int     g_bsum[NBLK];

// ---------------------------------------------------------------------------
// ego fp32 -> fp16 (concat fused)
// ---------------------------------------------------------------------------
__global__ void __launch_bounds__(256) convert_kernel(
    const float2* __restrict__ u, const float2* __restrict__ it,
    __half2* __restrict__ egoH)
{
    int i = blockIdx.x * blockDim.x + threadIdx.x;
    const int total = N_NODES * DH2;
    const int nu = N_USERS * DF2;
    if (i < total) {
        float2 v = (i < nu) ? __ldg(u + i) : __ldg(it + (i - nu));
        egoH[i] = __float22half2_rn(v);
    }
}

// ---------------------------------------------------------------------------
// CSR build: histogram -> 2-level exclusive scan -> scatter permute
// ---------------------------------------------------------------------------
__global__ void __launch_bounds__(256) hist_kernel(const int4* __restrict__ row4)
{
    int i = blockIdx.x * blockDim.x + threadIdx.x;
    if (i < NNZ / 4) {
        int4 r = __ldg(row4 + i);
        atomicAdd(&g_cnt[r.x], 1);
        atomicAdd(&g_cnt[r.y], 1);
        atomicAdd(&g_cnt[r.z], 1);
        atomicAdd(&g_cnt[r.w], 1);
    }
}

__global__ void __launch_bounds__(SCAN_BLK) scan1_kernel()
{
    __shared__ int s[SCAN_BLK];
    int gid = blockIdx.x * SCAN_BLK + threadIdx.x;
    int c = (gid < N_NODES) ? g_cnt[gid] : 0;
    s[threadIdx.x] = c;
    __syncthreads();
    #pragma unroll
    for (int off = 1; off < SCAN_BLK; off <<= 1) {
        int t = (threadIdx.x >= off) ? s[threadIdx.x - off] : 0;
        __syncthreads();
        s[threadIdx.x] += t;
        __syncthreads();
    }
    if (gid < N_NODES) g_rowptr[gid] = s[threadIdx.x] - c;
    if (threadIdx.x == SCAN_BLK - 1) g_bsum[blockIdx.x] = s[SCAN_BLK - 1];
}

__global__ void __launch_bounds__(256) scan2_kernel()
{
    __shared__ int s[256];
    int c = (threadIdx.x < NBLK) ? g_bsum[threadIdx.x] : 0;
    s[threadIdx.x] = c;
    __syncthreads();
    #pragma unroll
    for (int off = 1; off < 256; off <<= 1) {
        int t = (threadIdx.x >= off) ? s[threadIdx.x - off] : 0;
        __syncthreads();
        s[threadIdx.x] += t;
        __syncthreads();
    }
    if (threadIdx.x < NBLK) g_bsum[threadIdx.x] = s[threadIdx.x] - c;
}

__global__ void __launch_bounds__(256) scan3_kernel()
{
    int i = blockIdx.x * blockDim.x + threadIdx.x;
    if (i < N_NODES) {
        int v = g_rowptr[i] + g_bsum[i >> 10];
        g_rowptr[i] = v;
        g_wp[i] = v;
    }
    if (i == 0) g_rowptr[N_NODES] = NNZ;
}

__global__ void __launch_bounds__(256) scatter_kernel(
    const int* __restrict__ row, const int* __restrict__ col,
    const float* __restrict__ vals)
{
    int e = blockIdx.x * blockDim.x + threadIdx.x;
    if (e >= NNZ) return;
    int r = __ldg(row + e);
    int pos = atomicAdd(&g_wp[r], 1);
    g_colv[pos] = make_int2(__ldg(col + e), __float_as_int(__ldg(vals + e)));
}

// ---------------------------------------------------------------------------
// Gather SpMM hop over fp16 X: one warp per output node, lane owns one half2
// (dims 2l, 2l+1). 128B coalesced gather per edge. fp32 accumulation.
// MODE 1: out_all = y/3, out_layer = y, yh = fp16(y)
// MODE 2: out_all += y/3, yh = fp16(y)
// MODE 3: out_all += y/3
// ---------------------------------------------------------------------------
template<int MODE>
__global__ void __launch_bounds__(256) hop_kernel(
    const __half2* __restrict__ xh, __half2* __restrict__ yh,
    float2* __restrict__ out_all, float2* __restrict__ out_layer)
{
    int warp = (blockIdx.x * blockDim.x + threadIdx.x) >> 5;
    int lane = threadIdx.x & 31;
    if (warp >= N_NODES) return;

    int beg = g_rowptr[warp];
    int end = g_rowptr[warp + 1];

    float ax = 0.0f, ay = 0.0f;
    #pragma unroll 4
    for (int e = beg; e < end; e++) {
        int2 cv = __ldg(&g_colv[e]);                       // warp-uniform
        float v = __int_as_float(cv.y);
        __half2 h = __ldg(xh + (size_t)cv.x * DH2 + lane); // 128B/warp
        float2 xv = __half22float2(h);
        ax = fmaf(v, xv.x, ax);
        ay = fmaf(v, xv.y, ay);
    }

    size_t o = (size_t)warp * DH2 + lane;
    const float s = 1.0f / 3.0f;
    if (MODE == 1) {
        yh[o]        = __floats2half2_rn(ax, ay);
        out_all[o]   = make_float2(ax * s, ay * s);
        out_layer[o] = make_float2(ax, ay);
    } else if (MODE == 2) {
        yh[o] = __floats2half2_rn(ax, ay);
        float2 cu = out_all[o];
        out_all[o] = make_float2(cu.x + ax * s, cu.y + ay * s);
    } else {
        float2 cu = out_all[o];
        out_all[o] = make_float2(cu.x + ax * s, cu.y + ay * s);
    }
}

// ---------------------------------------------------------------------------
extern "C" void kernel_launch(void* const* d_in, const int* in_sizes, int n_in,
                              void* d_out, int out_size)
{
    const float2* user_e = (const float2*)d_in[0];
    const float2* item_e = (const float2*)d_in[1];
    const int*    row    = (const int*)d_in[2];
    const int*    col    = (const int*)d_in[3];
    const float*  vals   = (const float*)d_in[4];

    float2* out_all   = (float2*)d_out;
    float2* out_layer = out_all + (size_t)N_NODES * DF2;

    void* cntAddr;
    cudaGetSymbolAddress(&cntAddr, g_cnt);
    __half2 *egoH, *bufA, *bufB;
    cudaGetSymbolAddress((void**)&egoH, g_egoH);
    cudaGetSymbolAddress((void**)&bufA, g_bufA);
    cudaGetSymbolAddress((void**)&bufB, g_bufB);

    const int edgeBlocks  = (NNZ + 255) / 256;
    const int edge4Blocks = (NNZ / 4 + 255) / 256;
    const int nodeBlocks  = (N_NODES + 255) / 256;
    const int elemBlocks  = (N_NODES * DH2 + 255) / 256;
    const int hopBlocks   = (N_NODES * 32 + 255) / 256;

    // ---- fp16 ego + CSR build ----
    convert_kernel<<<elemBlocks, 256>>>(user_e, item_e, egoH);
    cudaMemsetAsync(cntAddr, 0, N_NODES * sizeof(int));
    hist_kernel<<<edge4Blocks, 256>>>((const int4*)row);
    scan1_kernel<<<NBLK, SCAN_BLK>>>();
    scan2_kernel<<<1, 256>>>();
    scan3_kernel<<<nodeBlocks, 256>>>();
    scatter_kernel<<<edgeBlocks, 256>>>(row, col, vals);

    // ---- 3 hops, fp16 gathers, fp32 accumulate, fused epilogues ----
    hop_kernel<1><<<hopBlocks, 256>>>(egoH, bufA, out_all, out_layer);
    hop_kernel<2><<<hopBlocks, 256>>>(bufA, bufB, out_all, out_layer);
    hop_kernel<3><<<hopBlocks, 256>>>(bufB, nullptr, out_all, out_layer);
}

// round 7
// speedup vs baseline: 2.6306x; 1.1692x over previous
#include <cuda_runtime.h>
#include <cuda_fp16.h>
#include <cstdint>

#define N_USERS 100000
#define N_ITEMS 50000
#define N_NODES 150000
#define D 64
#define DH2 32             // D/2 half2 per node row (128B)
#define DU2 16             // D/4 uint2 per node row (128B)
#define DF2 32             // D/2 float2 per node row (256B)
#define NNZ 4800000
#define SCAN_BLK 1024
#define NBLK ((N_NODES + SCAN_BLK - 1) / SCAN_BLK)   // 147

// ---------------- device-global scratch (no allocations allowed) -----------
__device__ uint2 g_egoH[N_NODES * DU2];   // 19.2 MB fp16 ego
__device__ uint2 g_bufA[N_NODES * DU2];   // 19.2 MB hop-1 out (fp16)
__device__ uint2 g_bufB[N_NODES * DU2];   // 19.2 MB hop-2 out (fp16)
__device__ int2  g_colv[NNZ];             // 38.4 MB {col, val-bits}, CSR order
__device__ int   g_cnt[N_NODES];
__device__ int   g_rowptr[N_NODES + 1];
__device__ int   g_wp[N_NODES];
__device__ int   g_bsum[NBLK];

// ---------------------------------------------------------------------------
// ego fp32 -> fp16 (concat fused)
// ---------------------------------------------------------------------------
__global__ void __launch_bounds__(256) convert_kernel(
    const float2* __restrict__ u, const float2* __restrict__ it,
    __half2* __restrict__ egoH)
{
    int i = blockIdx.x * blockDim.x + threadIdx.x;
    const int total = N_NODES * DH2;
    const int nu = N_USERS * DF2;
    if (i < total) {
        float2 v = (i < nu) ? __ldg(u + i) : __ldg(it + (i - nu));
        egoH[i] = __float22half2_rn(v);
    }
}

// ---------------------------------------------------------------------------
// CSR build: histogram -> 2-level exclusive scan -> scatter permute
// ---------------------------------------------------------------------------
__global__ void __launch_bounds__(256) hist_kernel(const int4* __restrict__ row4)
{
    int i = blockIdx.x * blockDim.x + threadIdx.x;
    if (i < NNZ / 4) {
        int4 r = __ldg(row4 + i);
        atomicAdd(&g_cnt[r.x], 1);
        atomicAdd(&g_cnt[r.y], 1);
        atomicAdd(&g_cnt[r.z], 1);
        atomicAdd(&g_cnt[r.w], 1);
    }
}

__global__ void __launch_bounds__(SCAN_BLK) scan1_kernel()
{
    __shared__ int s[SCAN_BLK];
    int gid = blockIdx.x * SCAN_BLK + threadIdx.x;
    int c = (gid < N_NODES) ? g_cnt[gid] : 0;
    s[threadIdx.x] = c;
    __syncthreads();
    #pragma unroll
    for (int off = 1; off < SCAN_BLK; off <<= 1) {
        int t = (threadIdx.x >= off) ? s[threadIdx.x - off] : 0;
        __syncthreads();
        s[threadIdx.x] += t;
        __syncthreads();
    }
    if (gid < N_NODES) g_rowptr[gid] = s[threadIdx.x] - c;
    if (threadIdx.x == SCAN_BLK - 1) g_bsum[blockIdx.x] = s[SCAN_BLK - 1];
}

__global__ void __launch_bounds__(256) scan2_kernel()
{
    __shared__ int s[256];
    int c = (threadIdx.x < NBLK) ? g_bsum[threadIdx.x] : 0;
    s[threadIdx.x] = c;
    __syncthreads();
    #pragma unroll
    for (int off = 1; off < 256; off <<= 1) {
        int t = (threadIdx.x >= off) ? s[threadIdx.x - off] : 0;
        __syncthreads();
        s[threadIdx.x] += t;
        __syncthreads();
    }
    if (threadIdx.x < NBLK) g_bsum[threadIdx.x] = s[threadIdx.x] - c;
}

__global__ void __launch_bounds__(256) scan3_kernel()
{
    int i = blockIdx.x * blockDim.x + threadIdx.x;
    if (i < N_NODES) {
        int v = g_rowptr[i] + g_bsum[i >> 10];
        g_rowptr[i] = v;
        g_wp[i] = v;
    }
    if (i == 0) g_rowptr[N_NODES] = NNZ;
}

__global__ void __launch_bounds__(256) scatter_kernel(
    const int* __restrict__ row, const int* __restrict__ col,
    const float* __restrict__ vals)
{
    int e = blockIdx.x * blockDim.x + threadIdx.x;
    if (e >= NNZ) return;
    int r = __ldg(row + e);
    int pos = atomicAdd(&g_wp[r], 1);
    g_colv[pos] = make_int2(__ldg(col + e), __float_as_int(__ldg(vals + e)));
}

// ---------------------------------------------------------------------------
// Gather SpMM hop, high-MLP variant:
//   2 rows per warp, 16 lanes per row; lane owns 8B (4 dims) of the 128B row.
//   Edge metadata loaded cooperatively: 16 lanes load 16 colv entries in one
//   coalesced 128B transaction, then shfl-broadcast each entry -> 16
//   INDEPENDENT gather loads in flight per row (32 per warp).
// MODE 1: x=egoH; write bufA (fp16), out_all = y/3, out_layer = y
// MODE 2: x=bufA; write bufB (fp16), out_all += y/3
// MODE 3: x=bufB;                    out_all += y/3
// ---------------------------------------------------------------------------
template<int MODE>
__global__ void __launch_bounds__(256) hop_kernel(
    const uint2* __restrict__ xh, uint2* __restrict__ yh,
    float2* __restrict__ out_all, float2* __restrict__ out_layer)
{
    int gwarp = (blockIdx.x * blockDim.x + threadIdx.x) >> 5;
    int lane  = threadIdx.x & 31;
    int half  = lane >> 4;               // which row of the pair
    int sub   = lane & 15;               // lane within the row
    int row   = gwarp * 2 + half;
    if (row >= N_NODES) return;

    const unsigned mask = 0xFFFFu << (half << 4);
    int beg = g_rowptr[row];
    int end = g_rowptr[row + 1];

    float a0 = 0.f, a1 = 0.f, a2 = 0.f, a3 = 0.f;

    for (int base = beg; base < end; base += 16) {
        int idx = base + sub;
        int2 cv = (idx < end) ? __ldg(&g_colv[idx]) : make_int2(0, 0);
        #pragma unroll
        for (int j = 0; j < 16; j++) {
            int cx = __shfl_sync(mask, cv.x, j, 16);
            int vb = __shfl_sync(mask, cv.y, j, 16);
            if (base + j < end) {
                uint2 h = __ldg(xh + (size_t)cx * DU2 + sub);   // 128B/row
                float v = __int_as_float(vb);
                float2 f0 = __half22float2(*reinterpret_cast<__half2*>(&h.x));
                float2 f1 = __half22float2(*reinterpret_cast<__half2*>(&h.y));
                a0 = fmaf(v, f0.x, a0);
                a1 = fmaf(v, f0.y, a1);
                a2 = fmaf(v, f1.x, a2);
                a3 = fmaf(v, f1.y, a3);
            }
        }
    }

    const float s = 1.0f / 3.0f;
    size_t oh = (size_t)row * DU2 + sub;          // fp16 buffer slot
    size_t of = (size_t)row * DF2 + sub * 2;      // fp32 float2 slot (x2)

    if (MODE == 1 || MODE == 2) {
        uint2 packed;
        __half2 p0 = __floats2half2_rn(a0, a1);
        __half2 p1 = __floats2half2_rn(a2, a3);
        packed.x = *reinterpret_cast<unsigned*>(&p0);
        packed.y = *reinterpret_cast<unsigned*>(&p1);
        yh[oh] = packed;
    }
    if (MODE == 1) {
        out_all[of]     = make_float2(a0 * s, a1 * s);
        out_all[of + 1] = make_float2(a2 * s, a3 * s);
        out_layer[of]     = make_float2(a0, a1);
        out_layer[of + 1] = make_float2(a2, a3);
    } else {
        float2 c0 = out_all[of];
        float2 c1 = out_all[of + 1];
        out_all[of]     = make_float2(c0.x + a0 * s, c0.y + a1 * s);
        out_all[of + 1] = make_float2(c1.x + a2 * s, c1.y + a3 * s);
    }
}

// ---------------------------------------------------------------------------
extern "C" void kernel_launch(void* const* d_in, const int* in_sizes, int n_in,
                              void* d_out, int out_size)
{
    const float2* user_e = (const float2*)d_in[0];
    const float2* item_e = (const float2*)d_in[1];
    const int*    row    = (const int*)d_in[2];
    const int*    col    = (const int*)d_in[3];
    const float*  vals   = (const float*)d_in[4];

    float2* out_all   = (float2*)d_out;
    float2* out_layer = out_all + (size_t)N_NODES * DF2;

    void* cntAddr;
    cudaGetSymbolAddress(&cntAddr, g_cnt);
    uint2 *egoH, *bufA, *bufB;
    cudaGetSymbolAddress((void**)&egoH, g_egoH);
    cudaGetSymbolAddress((void**)&bufA, g_bufA);
    cudaGetSymbolAddress((void**)&bufB, g_bufB);

    const int edgeBlocks  = (NNZ + 255) / 256;
    const int edge4Blocks = (NNZ / 4 + 255) / 256;
    const int nodeBlocks  = (N_NODES + 255) / 256;
    const int elemBlocks  = (N_NODES * DH2 + 255) / 256;
    const int hopWarps    = (N_NODES + 1) / 2;              // 2 rows per warp
    const int hopBlocks   = (hopWarps * 32 + 255) / 256;

    // ---- fp16 ego + CSR build ----
    convert_kernel<<<elemBlocks, 256>>>(user_e, item_e, (__half2*)egoH);
    cudaMemsetAsync(cntAddr, 0, N_NODES * sizeof(int));
    hist_kernel<<<edge4Blocks, 256>>>((const int4*)row);
    scan1_kernel<<<NBLK, SCAN_BLK>>>();
    scan2_kernel<<<1, 256>>>();
    scan3_kernel<<<nodeBlocks, 256>>>();
    scatter_kernel<<<edgeBlocks, 256>>>(row, col, vals);

    // ---- 3 hops, high-MLP fp16 gathers, fp32 accumulate ----
    hop_kernel<1><<<hopBlocks, 256>>>(egoH, bufA, out_all, out_layer);
    hop_kernel<2><<<hopBlocks, 256>>>(bufA, bufB, out_all, out_layer);
    hop_kernel<3><<<hopBlocks, 256>>>(bufB, nullptr, out_all, out_layer);
}

// round 8
// speedup vs baseline: 2.6669x; 1.0138x over previous
#include <cuda_runtime.h>
#include <cuda_fp16.h>
#include <cstdint>

#define N_USERS 100000
#define N_ITEMS 50000
#define N_NODES 150000
#define D 64
#define DH2 32             // D/2 half2 per node row (128B)
#define DU2 16             // D/4 uint2 per node row (128B)
#define DF2 32             // D/2 float2 per node row (256B)
#define NNZ 4800000
#define SCAN_BLK 1024
#define NBLK ((N_NODES + SCAN_BLK - 1) / SCAN_BLK)   // 147

// ---------------- device-global scratch (no allocations allowed) -----------
__device__ uint2 g_egoH[N_NODES * DU2];   // 19.2 MB fp16 ego
__device__ uint2 g_bufA[N_NODES * DU2];   // 19.2 MB hop-1 out (fp16)
__device__ uint2 g_bufB[N_NODES * DU2];   // 19.2 MB hop-2 out (fp16)
__device__ int2  g_colv[NNZ];             // 38.4 MB {col, val-bits}, CSR order
__device__ int   g_cnt[N_NODES];
__device__ int   g_rowptr[N_NODES + 1];
__device__ int   g_wp[N_NODES];
__device__ int   g_bsum[NBLK];

// ---------------------------------------------------------------------------
// ego fp32 -> fp16 (concat fused)
// ---------------------------------------------------------------------------
__global__ void __launch_bounds__(256) convert_kernel(
    const float2* __restrict__ u, const float2* __restrict__ it,
    __half2* __restrict__ egoH)
{
    int i = blockIdx.x * blockDim.x + threadIdx.x;
    const int total = N_NODES * DH2;
    const int nu = N_USERS * DF2;
    if (i < total) {
        float2 v = (i < nu) ? __ldg(u + i) : __ldg(it + (i - nu));
        egoH[i] = __float22half2_rn(v);
    }
}

// ---------------------------------------------------------------------------
// CSR build: histogram -> 2-level exclusive scan -> scatter permute
// ---------------------------------------------------------------------------
__global__ void __launch_bounds__(256) hist_kernel(const int4* __restrict__ row4)
{
    int i = blockIdx.x * blockDim.x + threadIdx.x;
    if (i < NNZ / 4) {
        int4 r = __ldcs(row4 + i);
        atomicAdd(&g_cnt[r.x], 1);
        atomicAdd(&g_cnt[r.y], 1);
        atomicAdd(&g_cnt[r.z], 1);
        atomicAdd(&g_cnt[r.w], 1);
    }
}

__global__ void __launch_bounds__(SCAN_BLK) scan1_kernel()
{
    __shared__ int s[SCAN_BLK];
    int gid = blockIdx.x * SCAN_BLK + threadIdx.x;
    int c = (gid < N_NODES) ? g_cnt[gid] : 0;
    s[threadIdx.x] = c;
    __syncthreads();
    #pragma unroll
    for (int off = 1; off < SCAN_BLK; off <<= 1) {
        int t = (threadIdx.x >= off) ? s[threadIdx.x - off] : 0;
        __syncthreads();
        s[threadIdx.x] += t;
        __syncthreads();
    }
    if (gid < N_NODES) g_rowptr[gid] = s[threadIdx.x] - c;
    if (threadIdx.x == SCAN_BLK - 1) g_bsum[blockIdx.x] = s[SCAN_BLK - 1];
}

__global__ void __launch_bounds__(256) scan2_kernel()
{
    __shared__ int s[256];
    int c = (threadIdx.x < NBLK) ? g_bsum[threadIdx.x] : 0;
    s[threadIdx.x] = c;
    __syncthreads();
    #pragma unroll
    for (int off = 1; off < 256; off <<= 1) {
        int t = (threadIdx.x >= off) ? s[threadIdx.x - off] : 0;
        __syncthreads();
        s[threadIdx.x] += t;
        __syncthreads();
    }
    if (threadIdx.x < NBLK) g_bsum[threadIdx.x] = s[threadIdx.x] - c;
}

__global__ void __launch_bounds__(256) scan3_kernel()
{
    int i = blockIdx.x * blockDim.x + threadIdx.x;
    if (i < N_NODES) {
        int v = g_rowptr[i] + g_bsum[i >> 10];
        g_rowptr[i] = v;
        g_wp[i] = v;
    }
    if (i == 0) g_rowptr[N_NODES] = NNZ;
}

__global__ void __launch_bounds__(256) scatter_kernel(
    const int4* __restrict__ row4, const int4* __restrict__ col4,
    const float4* __restrict__ vals4)
{
    int i = blockIdx.x * blockDim.x + threadIdx.x;
    if (i >= NNZ / 4) return;
    int4   r = __ldcs(row4 + i);
    int4   c = __ldcs(col4 + i);
    float4 v = __ldcs(vals4 + i);
    int p0 = atomicAdd(&g_wp[r.x], 1);
    int p1 = atomicAdd(&g_wp[r.y], 1);
    int p2 = atomicAdd(&g_wp[r.z], 1);
    int p3 = atomicAdd(&g_wp[r.w], 1);
    __stcs(&g_colv[p0], make_int2(c.x, __float_as_int(v.x)));
    __stcs(&g_colv[p1], make_int2(c.y, __float_as_int(v.y)));
    __stcs(&g_colv[p2], make_int2(c.z, __float_as_int(v.z)));
    __stcs(&g_colv[p3], make_int2(c.w, __float_as_int(v.w)));
}

// ---------------------------------------------------------------------------
// Gather SpMM hop, high-MLP: 2 rows/warp, 16 lanes/row, lane owns 8B (4 dims).
// Cooperative colv chunk load (16 edges, one 128B transaction) -> 16
// independent shfl-fed gathers per row (32 outstanding per warp).
// Streaming hints: colv via __ldcs, outputs via __stcs; X gathers use default
// policy so the hot 19.2MB table stays L2-resident.
// MODE 1: x=egoH; yh=bufA, out_layer = y1
// MODE 2: x=bufA; yh=bufB
// MODE 3: x=bufB; out_all = (bufA + bufB + y3)/3
// ---------------------------------------------------------------------------
template<int MODE>
__global__ void __launch_bounds__(256) hop_kernel(
    const uint2* __restrict__ xh, uint2* __restrict__ yh,
    const uint2* __restrict__ y1h, const uint2* __restrict__ y2h,
    float2* __restrict__ out_all, float2* __restrict__ out_layer)
{
    int gwarp = (blockIdx.x * blockDim.x + threadIdx.x) >> 5;
    int lane  = threadIdx.x & 31;
    int half  = lane >> 4;
    int sub   = lane & 15;
    int row   = gwarp * 2 + half;
    if (row >= N_NODES) return;

    const unsigned mask = 0xFFFFu << (half << 4);
    int beg = g_rowptr[row];
    int end = g_rowptr[row + 1];

    float a0 = 0.f, a1 = 0.f, a2 = 0.f, a3 = 0.f;

    for (int base = beg; base < end; base += 16) {
        int idx = base + sub;
        int2 cv = (idx < end) ? __ldcs(&g_colv[idx]) : make_int2(0, 0);
        #pragma unroll
        for (int j = 0; j < 16; j++) {
            int cx = __shfl_sync(mask, cv.x, j, 16);
            int vb = __shfl_sync(mask, cv.y, j, 16);
            if (base + j < end) {
                uint2 h = __ldg(xh + (size_t)cx * DU2 + sub);   // hot table
                float v = __int_as_float(vb);
                float2 f0 = __half22float2(*reinterpret_cast<__half2*>(&h.x));
                float2 f1 = __half22float2(*reinterpret_cast<__half2*>(&h.y));
                a0 = fmaf(v, f0.x, a0);
                a1 = fmaf(v, f0.y, a1);
                a2 = fmaf(v, f1.x, a2);
                a3 = fmaf(v, f1.y, a3);
            }
        }
    }

    size_t oh = (size_t)row * DU2 + sub;          // fp16 buffer slot
    size_t of = (size_t)row * DF2 + sub * 2;      // fp32 float2 slot (x2)

    if (MODE == 1 || MODE == 2) {
        __half2 p0 = __floats2half2_rn(a0, a1);
        __half2 p1 = __floats2half2_rn(a2, a3);
        uint2 packed;
        packed.x = *reinterpret_cast<unsigned*>(&p0);
        packed.y = *reinterpret_cast<unsigned*>(&p1);
        __stcs(&yh[oh], packed);
    }
    if (MODE == 1) {
        __stcs(&out_layer[of],     make_float2(a0, a1));
        __stcs(&out_layer[of + 1], make_float2(a2, a3));
    }
    if (MODE == 3) {
        const float s = 1.0f / 3.0f;
        uint2 u1 = __ldcs(y1h + oh);
        uint2 u2 = __ldcs(y2h + oh);
        float2 b10 = __half22float2(*reinterpret_cast<__half2*>(&u1.x));
        float2 b11 = __half22float2(*reinterpret_cast<__half2*>(&u1.y));
        float2 b20 = __half22float2(*reinterpret_cast<__half2*>(&u2.x));
        float2 b21 = __half22float2(*reinterpret_cast<__half2*>(&u2.y));
        __stcs(&out_all[of],
               make_float2((b10.x + b20.x + a0) * s, (b10.y + b20.y + a1) * s));
        __stcs(&out_all[of + 1],
               make_float2((b11.x + b21.x + a2) * s, (b11.y + b21.y + a3) * s));
    }
}

// ---------------------------------------------------------------------------
extern "C" void kernel_launch(void* const* d_in, const int* in_sizes, int n_in,
                              void* d_out, int out_size)
{
    const float2* user_e = (const float2*)d_in[0];
    const float2* item_e = (const float2*)d_in[1];
    const int*    row    = (const int*)d_in[2];
    const int*    col    = (const int*)d_in[3];
    const float*  vals   = (const float*)d_in[4];

    float2* out_all   = (float2*)d_out;
    float2* out_layer = out_all + (size_t)N_NODES * DF2;

    void* cntAddr;
    cudaGetSymbolAddress(&cntAddr, g_cnt);
    uint2 *egoH, *bufA, *bufB;
    cudaGetSymbolAddress((void**)&egoH, g_egoH);
    cudaGetSymbolAddress((void**)&bufA, g_bufA);
    cudaGetSymbolAddress((void**)&bufB, g_bufB);

    const int edge4Blocks = (NNZ / 4 + 255) / 256;
    const int nodeBlocks  = (N_NODES + 255) / 256;
    const int elemBlocks  = (N_NODES * DH2 + 255) / 256;
    const int hopWarps    = (N_NODES + 1) / 2;              // 2 rows per warp
    const int hopBlocks   = (hopWarps * 32 + 255) / 256;

    // ---- fp16 ego + CSR build ----
    convert_kernel<<<elemBlocks, 256>>>(user_e, item_e, (__half2*)egoH);
    cudaMemsetAsync(cntAddr, 0, N_NODES * sizeof(int));
    hist_kernel<<<edge4Blocks, 256>>>((const int4*)row);
    scan1_kernel<<<NBLK, SCAN_BLK>>>();
    scan2_kernel<<<1, 256>>>();
    scan3_kernel<<<nodeBlocks, 256>>>();
    scatter_kernel<<<edge4Blocks, 256>>>((const int4*)row, (const int4*)col,
                                         (const float4*)vals);

    // ---- 3 hops; mean deferred to hop 3 (no out_all RMW chain) ----
    hop_kernel<1><<<hopBlocks, 256>>>(egoH, bufA, nullptr, nullptr,
                                      out_all, out_layer);
    hop_kernel<2><<<hopBlocks, 256>>>(bufA, bufB, nullptr, nullptr,
                                      out_all, out_layer);
    hop_kernel<3><<<hopBlocks, 256>>>(bufB, nullptr, bufA, bufB,
                                      out_all, out_layer);
}